// round 6
// baseline (speedup 1.0000x reference)
#include <cuda_runtime.h>
#include <cstdint>

#define BB 2
#define CC 64
#define CQ 16
#define DD 96
#define PP 9216                    // H*W
#define PDSTRIDE (PP*DD)           // per-channel stride in x
#define CPD (CC*PDSTRIDE)          // per-batch stride in x
#define PCHUNK 32
#define PCOUT 16

typedef unsigned long long u64;

__device__ double g_energy[BB*DD*DD];
__device__ int    g_nnz [BB*DD];
__device__ int    g_eidx[BB*DD*DD];
__device__ float  g_aval[BB*DD*DD];

// ---- packed f32x2 helpers (FFMA2 path only reachable via PTX) ----
__device__ __forceinline__ u64 pk2(float lo, float hi) {
    u64 r; asm("mov.b64 %0, {%1, %2};" : "=l"(r) : "f"(lo), "f"(hi)); return r;
}
__device__ __forceinline__ u64 bc2(float v) { return pk2(v, v); }
__device__ __forceinline__ void up2(float& lo, float& hi, u64 v) {
    asm("mov.b64 {%0, %1}, %2;" : "=f"(lo), "=f"(hi) : "l"(v));
}
__device__ __forceinline__ u64 ffma2(u64 a, u64 b, u64 c) {
    u64 d; asm("fma.rn.f32x2 %0, %1, %2, %3;" : "=l"(d) : "l"(a), "l"(b), "l"(c));
    return d;
}

// ===========================================================================
// Kernel A (R3 verbatim): energy via FFMA2 register tiles + fp64 atomics.
// ===========================================================================
__global__ void __launch_bounds__(256, 2) energy_k(
    const float* __restrict__ x,
    const float* __restrict__ Wq, const float* __restrict__ bq,
    const float* __restrict__ Wk, const float* __restrict__ bk)
{
    __shared__ __align__(16) float sWq[CQ*CC];
    __shared__ __align__(16) float sWk[CQ*CC];
    __shared__ __align__(16) float sX[CC*DD];
    __shared__ __align__(16) float sQ[CQ*DD];
    __shared__ __align__(16) float sK[CQ*DD];

    const int t  = threadIdx.x;
    const int b  = blockIdx.y;
    const int p0 = blockIdx.x * PCHUNK;

    for (int i = t; i < CQ*CC; i += 256) {
        sWq[i] = Wq[i];
        sWk[i] = Wk[i];
    }

    const int cqi = t >> 4;
    const int dxb = 6 * (t & 15);
    const float bq_s = bq[cqi];
    const float bk_s = bk[cqi];

    const int tx = t & 15;
    const int ty = t >> 4;

    u64 acc[6][3];
    #pragma unroll
    for (int i = 0; i < 6; ++i)
        #pragma unroll
        for (int j = 0; j < 3; ++j) acc[i][j] = 0ull;

    const float* xb = x + (size_t)b * CPD;

    for (int pp = 0; pp < PCHUNK; ++pp) {
        const int p = p0 + pp;
        __syncthreads();

        const float* xp = xb + (size_t)p * DD;
        #pragma unroll
        for (int r = 0; r < 12; ++r) {
            int i2 = t + r * 256;
            int c  = i2 / 48, dp = i2 % 48;
            float2 v = *reinterpret_cast<const float2*>(xp + (size_t)c * PDSTRIDE + 2*dp);
            *reinterpret_cast<float2*>(&sX[c*DD + 2*dp]) = v;
        }
        __syncthreads();

        u64 qa[3], ka[3];
        #pragma unroll
        for (int j = 0; j < 3; ++j) { qa[j] = bc2(bq_s); ka[j] = bc2(bk_s); }

        #pragma unroll 4
        for (int c4 = 0; c4 < CC; c4 += 4) {
            const float4 wq4 = *reinterpret_cast<const float4*>(&sWq[cqi*CC + c4]);
            const float4 wk4 = *reinterpret_cast<const float4*>(&sWk[cqi*CC + c4]);
            const float wq[4] = {wq4.x, wq4.y, wq4.z, wq4.w};
            const float wk[4] = {wk4.x, wk4.y, wk4.z, wk4.w};
            #pragma unroll
            for (int cc = 0; cc < 4; ++cc) {
                const int c = c4 + cc;
                u64 xv[3];
                #pragma unroll
                for (int j = 0; j < 3; ++j)
                    xv[j] = *reinterpret_cast<const u64*>(&sX[c*DD + dxb + 2*j]);
                const u64 wqb = bc2(wq[cc]);
                const u64 wkb = bc2(wk[cc]);
                #pragma unroll
                for (int j = 0; j < 3; ++j) {
                    qa[j] = ffma2(wqb, xv[j], qa[j]);
                    ka[j] = ffma2(wkb, xv[j], ka[j]);
                }
            }
        }
        #pragma unroll
        for (int j = 0; j < 3; ++j) {
            *reinterpret_cast<u64*>(&sQ[cqi*DD + dxb + 2*j]) = qa[j];
            *reinterpret_cast<u64*>(&sK[cqi*DD + dxb + 2*j]) = ka[j];
        }
        __syncthreads();

        #pragma unroll 2
        for (int cq = 0; cq < CQ; ++cq) {
            u64 kv[3];
            #pragma unroll
            for (int j = 0; j < 3; ++j)
                kv[j] = *reinterpret_cast<const u64*>(&sK[cq*DD + 6*ty + 2*j]);
            #pragma unroll
            for (int i = 0; i < 6; ++i) {
                const u64 qb = bc2(sQ[cq*DD + tx + 16*i]);
                #pragma unroll
                for (int j = 0; j < 3; ++j)
                    acc[i][j] = ffma2(qb, kv[j], acc[i][j]);
            }
        }
    }

    const size_t eb = (size_t)b * DD * DD;
    #pragma unroll
    for (int i = 0; i < 6; ++i)
        #pragma unroll
        for (int j = 0; j < 3; ++j) {
            float lo, hi;
            up2(lo, hi, acc[i][j]);
            const size_t base = eb + (size_t)(tx + 16*i)*DD + (6*ty + 2*j);
            atomicAdd(&g_energy[base],     (double)lo);
            atomicAdd(&g_energy[base + 1], (double)hi);
        }
}

// ===========================================================================
// Kernel B: row softmax + compaction into (e, a) lists with a > 1e-8.
// One warp per (b,d) row; 3 elements per lane.
// ===========================================================================
#define ATHRESH 1e-8f

__global__ void __launch_bounds__(128) softmax_k()
{
    const int w    = (blockIdx.x * blockDim.x + threadIdx.x) >> 5;
    const int lane = threadIdx.x & 31;
    if (w >= BB*DD) return;

    const double* er = g_energy + (size_t)w * DD;
    float v0 = (float)er[lane];
    float v1 = (float)er[lane + 32];
    float v2 = (float)er[lane + 64];

    float m = fmaxf(v0, fmaxf(v1, v2));
    #pragma unroll
    for (int o = 16; o > 0; o >>= 1) m = fmaxf(m, __shfl_xor_sync(0xffffffffu, m, o));

    float e0 = expf(v0 - m), e1 = expf(v1 - m), e2 = expf(v2 - m);
    float s = e0 + e1 + e2;
    #pragma unroll
    for (int o = 16; o > 0; o >>= 1) s += __shfl_xor_sync(0xffffffffu, s, o);

    const float inv = 1.0f / s;
    const float a[3] = { e0 * inv, e1 * inv, e2 * inv };

    // compact entries with a > ATHRESH into g_eidx/g_aval[w][...]
    int* ei = g_eidx + (size_t)w * DD;
    float* av = g_aval + (size_t)w * DD;
    const unsigned lmask = (1u << lane) - 1u;
    int base = 0;
    #pragma unroll
    for (int sct = 0; sct < 3; ++sct) {
        const bool keep = a[sct] > ATHRESH;
        const unsigned mask = __ballot_sync(0xffffffffu, keep);
        if (keep) {
            const int idx = base + __popc(mask & lmask);
            ei[idx] = lane + 32*sct;
            av[idx] = a[sct];
        }
        base += __popc(mask);
    }
    if (lane == 0) g_nnz[w] = base;
}

// ===========================================================================
// Kernel C: out[b,c,p,d] = gamma * sum_{k in list(d)} a_k * V[c,e_k] + x[c,p,d]
// where V = Wv X_p + bv. Lists resident in SMEM for the block (same b).
// X double-buffered (LDG->reg prefetch), V recomputed per p (R3 math).
// ===========================================================================
#define VTS 98
#define O_WV  0
#define O_X0  (O_WV + CC*CC*4)                  // 16384
#define O_V   (O_X0 + 2*CC*DD*4)                // 65536
#define O_NNZ (O_V  + CC*VTS*4)                 // 90624
#define O_EI  (O_NNZ + DD*4)                    // 91008
#define O_AV  (O_EI + DD*DD*4)                  // 127872
#define O_TOTAL (O_AV + DD*DD*4)                // 164736 bytes

__global__ void __launch_bounds__(256) out_k(
    const float* __restrict__ x, const float* __restrict__ Wv,
    const float* __restrict__ bv, const float* __restrict__ gamma,
    float* __restrict__ out)
{
    extern __shared__ __align__(16) unsigned char osm[];
    float* sWv  = (float*)(osm + O_WV);
    float* sXb[2] = { (float*)(osm + O_X0), (float*)(osm + O_X0) + CC*DD };
    float* sV   = (float*)(osm + O_V);          // [c][e] stride 98
    int*   sNnz = (int*)  (osm + O_NNZ);
    int*   sEi  = (int*)  (osm + O_EI);         // [d][96]
    float* sAv  = (float*)(osm + O_AV);         // [d][96]

    const int t  = threadIdx.x;
    const int b  = blockIdx.y;
    const int p0 = blockIdx.x * PCOUT;
    const int tx = t & 15;                      // e-group for V compute
    const int ty = t >> 4;                      // c-group for V compute
    const int exb = 6 * tx;
    const int lane = t & 31;
    const int wrp  = t >> 5;

    for (int i = t; i < CC*CC; i += 256) sWv[i] = Wv[i];
    for (int i = t; i < DD; i += 256) sNnz[i] = g_nnz[b*DD + i];
    for (int i = t; i < DD*DD; i += 256) {
        sEi[i] = g_eidx[(size_t)b*DD*DD + i];
        sAv[i] = g_aval[(size_t)b*DD*DD + i];
    }
    const float g = gamma[0];
    float bvv[4];
    #pragma unroll
    for (int k = 0; k < 4; ++k) bvv[k] = bv[4*ty + k];

    const float* xb = x   + (size_t)b * CPD;
    float*       ob = out + (size_t)b * CPD;

    float2 r[12];
    #define LDG_SLAB(P)  {                                                      \
        const float* xp = xb + (size_t)(P) * DD;                                \
        _Pragma("unroll")                                                       \
        for (int rr = 0; rr < 12; ++rr) {                                       \
            int i2 = t + rr*256;                                                \
            int c = i2 / 48, dp = i2 % 48;                                      \
            r[rr] = *reinterpret_cast<const float2*>(xp + (size_t)c * PDSTRIDE + 2*dp); } }
    #define STS_SLAB(BUF) {                                                     \
        _Pragma("unroll")                                                       \
        for (int rr = 0; rr < 12; ++rr) {                                       \
            int i2 = t + rr*256;                                                \
            int c = i2 / 48, dp = i2 % 48;                                      \
            *reinterpret_cast<float2*>(&(BUF)[c*DD + 2*dp]) = r[rr]; } }

    // ---- prologue: first slab ----
    LDG_SLAB(p0);
    STS_SLAB(sXb[0]);
    __syncthreads();                            // Wv, lists, X0 visible

    for (int pp = 0; pp < PCOUT; ++pp) {
        const int p = p0 + pp;
        const float* sX = sXb[pp & 1];

        if (pp + 1 < PCOUT) LDG_SLAB(p0 + pp + 1);

        // ---- V = Wv X + bv  (4 c x 3 e-pairs per thread), R3 math ----
        {
            u64 vv[4][3];
            #pragma unroll
            for (int k = 0; k < 4; ++k)
                #pragma unroll
                for (int j = 0; j < 3; ++j) vv[k][j] = bc2(bvv[k]);

            #pragma unroll 2
            for (int c2 = 0; c2 < CC; c2 += 2) {
                u64 x0[3], x1[3];
                #pragma unroll
                for (int j = 0; j < 3; ++j) {
                    x0[j] = *reinterpret_cast<const u64*>(&sX[c2*DD + exb + 2*j]);
                    x1[j] = *reinterpret_cast<const u64*>(&sX[(c2+1)*DD + exb + 2*j]);
                }
                #pragma unroll
                for (int k = 0; k < 4; ++k) {
                    const u64 w2 = *reinterpret_cast<const u64*>(&sWv[(4*ty + k)*CC + c2]);
                    float wlo, whi; up2(wlo, whi, w2);
                    const u64 wb0 = bc2(wlo), wb1 = bc2(whi);
                    #pragma unroll
                    for (int j = 0; j < 3; ++j) {
                        vv[k][j] = ffma2(wb0, x0[j], vv[k][j]);
                        vv[k][j] = ffma2(wb1, x1[j], vv[k][j]);
                    }
                }
            }
            #pragma unroll
            for (int k = 0; k < 4; ++k)
                #pragma unroll
                for (int j = 0; j < 3; ++j)
                    *reinterpret_cast<u64*>(&sV[(4*ty + k)*VTS + exb + 2*j]) = vv[k][j];
        }
        __syncthreads();                        // V ready

        // ---- gather: lanes over d (coalesced STG), warps over c ----
        #pragma unroll
        for (int ci = 0; ci < 8; ++ci) {
            const int c = wrp + 8*ci;
            const float* vrow = &sV[c*VTS];
            const float* xrow = &sX[c*DD];
            float* orow = ob + (size_t)c * PDSTRIDE + (size_t)p * DD;
            #pragma unroll
            for (int dd = 0; dd < 3; ++dd) {
                const int d = lane + 32*dd;
                const int n = sNnz[d];
                float acc = 0.f;
                for (int k = 0; k < n; ++k)
                    acc = fmaf(sAv[d*DD + k], vrow[sEi[d*DD + k]], acc);
                orow[d] = fmaf(g, acc, xrow[d]);
            }
        }

        if (pp + 1 < PCOUT) STS_SLAB(sXb[(pp + 1) & 1]);
        __syncthreads();                        // gather done; next X ready
    }
    #undef LDG_SLAB
    #undef STS_SLAB
}

// ---------------------------------------------------------------------------
extern "C" void kernel_launch(void* const* d_in, const int* in_sizes, int n_in,
                              void* d_out, int out_size)
{
    const float* x  = (const float*)d_in[0];
    const float* Wq = (const float*)d_in[1];
    const float* bq = (const float*)d_in[2];
    const float* Wk = (const float*)d_in[3];
    const float* bk = (const float*)d_in[4];
    const float* Wv = (const float*)d_in[5];
    const float* bv = (const float*)d_in[6];
    const float* gm = (const float*)d_in[7];
    float* out = (float*)d_out;

    void* eptr = nullptr;
    cudaGetSymbolAddress(&eptr, g_energy);
    cudaMemsetAsync(eptr, 0, sizeof(double)*BB*DD*DD, 0);

    energy_k<<<dim3(PP/PCHUNK, BB), 256>>>(x, Wq, bq, Wk, bk);

    softmax_k<<<(BB*DD*32 + 127)/128, 128>>>();

    cudaFuncSetAttribute(out_k, cudaFuncAttributeMaxDynamicSharedMemorySize, O_TOTAL);
    out_k<<<dim3(PP/PCOUT, BB), 256, O_TOTAL>>>(x, Wv, bv, gm, out);
}

// round 7
// speedup vs baseline: 2.2642x; 2.2642x over previous
#include <cuda_runtime.h>
#include <cstdint>

#define BB 2
#define CC 64
#define CQ 16
#define DD 96
#define PP 9216                    // H*W
#define PDSTRIDE (PP*DD)           // per-channel stride in x
#define CPD (CC*PDSTRIDE)          // per-batch stride in x
#define PCHUNK 32
#define PCOUT 16

typedef unsigned long long u64;

__device__ double g_energy[BB*DD*DD];
__device__ int    g_nnz [BB*DD];
__device__ int    g_eidx[BB*DD*DD];
__device__ float  g_aval[BB*DD*DD];

// ---- packed f32x2 helpers (FFMA2 path only reachable via PTX) ----
__device__ __forceinline__ u64 pk2(float lo, float hi) {
    u64 r; asm("mov.b64 %0, {%1, %2};" : "=l"(r) : "f"(lo), "f"(hi)); return r;
}
__device__ __forceinline__ u64 bc2(float v) { return pk2(v, v); }
__device__ __forceinline__ void up2(float& lo, float& hi, u64 v) {
    asm("mov.b64 {%0, %1}, %2;" : "=f"(lo), "=f"(hi) : "l"(v));
}
__device__ __forceinline__ u64 ffma2(u64 a, u64 b, u64 c) {
    u64 d; asm("fma.rn.f32x2 %0, %1, %2, %3;" : "=l"(d) : "l"(a), "l"(b), "l"(c));
    return d;
}

// ===========================================================================
// Kernel A (R3 verbatim): energy via FFMA2 register tiles + fp64 atomics.
// ===========================================================================
__global__ void __launch_bounds__(256, 2) energy_k(
    const float* __restrict__ x,
    const float* __restrict__ Wq, const float* __restrict__ bq,
    const float* __restrict__ Wk, const float* __restrict__ bk)
{
    __shared__ __align__(16) float sWq[CQ*CC];
    __shared__ __align__(16) float sWk[CQ*CC];
    __shared__ __align__(16) float sX[CC*DD];
    __shared__ __align__(16) float sQ[CQ*DD];
    __shared__ __align__(16) float sK[CQ*DD];

    const int t  = threadIdx.x;
    const int b  = blockIdx.y;
    const int p0 = blockIdx.x * PCHUNK;

    for (int i = t; i < CQ*CC; i += 256) {
        sWq[i] = Wq[i];
        sWk[i] = Wk[i];
    }

    const int cqi = t >> 4;
    const int dxb = 6 * (t & 15);
    const float bq_s = bq[cqi];
    const float bk_s = bk[cqi];

    const int tx = t & 15;
    const int ty = t >> 4;

    u64 acc[6][3];
    #pragma unroll
    for (int i = 0; i < 6; ++i)
        #pragma unroll
        for (int j = 0; j < 3; ++j) acc[i][j] = 0ull;

    const float* xb = x + (size_t)b * CPD;

    for (int pp = 0; pp < PCHUNK; ++pp) {
        const int p = p0 + pp;
        __syncthreads();

        const float* xp = xb + (size_t)p * DD;
        #pragma unroll
        for (int r = 0; r < 12; ++r) {
            int i2 = t + r * 256;
            int c  = i2 / 48, dp = i2 % 48;
            float2 v = *reinterpret_cast<const float2*>(xp + (size_t)c * PDSTRIDE + 2*dp);
            *reinterpret_cast<float2*>(&sX[c*DD + 2*dp]) = v;
        }
        __syncthreads();

        u64 qa[3], ka[3];
        #pragma unroll
        for (int j = 0; j < 3; ++j) { qa[j] = bc2(bq_s); ka[j] = bc2(bk_s); }

        #pragma unroll 4
        for (int c4 = 0; c4 < CC; c4 += 4) {
            const float4 wq4 = *reinterpret_cast<const float4*>(&sWq[cqi*CC + c4]);
            const float4 wk4 = *reinterpret_cast<const float4*>(&sWk[cqi*CC + c4]);
            const float wq[4] = {wq4.x, wq4.y, wq4.z, wq4.w};
            const float wk[4] = {wk4.x, wk4.y, wk4.z, wk4.w};
            #pragma unroll
            for (int cc = 0; cc < 4; ++cc) {
                const int c = c4 + cc;
                u64 xv[3];
                #pragma unroll
                for (int j = 0; j < 3; ++j)
                    xv[j] = *reinterpret_cast<const u64*>(&sX[c*DD + dxb + 2*j]);
                const u64 wqb = bc2(wq[cc]);
                const u64 wkb = bc2(wk[cc]);
                #pragma unroll
                for (int j = 0; j < 3; ++j) {
                    qa[j] = ffma2(wqb, xv[j], qa[j]);
                    ka[j] = ffma2(wkb, xv[j], ka[j]);
                }
            }
        }
        #pragma unroll
        for (int j = 0; j < 3; ++j) {
            *reinterpret_cast<u64*>(&sQ[cqi*DD + dxb + 2*j]) = qa[j];
            *reinterpret_cast<u64*>(&sK[cqi*DD + dxb + 2*j]) = ka[j];
        }
        __syncthreads();

        #pragma unroll 2
        for (int cq = 0; cq < CQ; ++cq) {
            u64 kv[3];
            #pragma unroll
            for (int j = 0; j < 3; ++j)
                kv[j] = *reinterpret_cast<const u64*>(&sK[cq*DD + 6*ty + 2*j]);
            #pragma unroll
            for (int i = 0; i < 6; ++i) {
                const u64 qb = bc2(sQ[cq*DD + tx + 16*i]);
                #pragma unroll
                for (int j = 0; j < 3; ++j)
                    acc[i][j] = ffma2(qb, kv[j], acc[i][j]);
            }
        }
    }

    const size_t eb = (size_t)b * DD * DD;
    #pragma unroll
    for (int i = 0; i < 6; ++i)
        #pragma unroll
        for (int j = 0; j < 3; ++j) {
            float lo, hi;
            up2(lo, hi, acc[i][j]);
            const size_t base = eb + (size_t)(tx + 16*i)*DD + (6*ty + 2*j);
            atomicAdd(&g_energy[base],     (double)lo);
            atomicAdd(&g_energy[base + 1], (double)hi);
        }
}

// ===========================================================================
// Kernel B: row softmax + compaction into (e, a) lists with a > 1e-8.
// One warp per (b,d) row; 3 elements per lane.
// ===========================================================================
#define ATHRESH 1e-8f

__global__ void __launch_bounds__(128) softmax_k()
{
    const int w    = (blockIdx.x * blockDim.x + threadIdx.x) >> 5;
    const int lane = threadIdx.x & 31;
    if (w >= BB*DD) return;

    const double* er = g_energy + (size_t)w * DD;
    float v0 = (float)er[lane];
    float v1 = (float)er[lane + 32];
    float v2 = (float)er[lane + 64];

    float m = fmaxf(v0, fmaxf(v1, v2));
    #pragma unroll
    for (int o = 16; o > 0; o >>= 1) m = fmaxf(m, __shfl_xor_sync(0xffffffffu, m, o));

    float e0 = expf(v0 - m), e1 = expf(v1 - m), e2 = expf(v2 - m);
    float s = e0 + e1 + e2;
    #pragma unroll
    for (int o = 16; o > 0; o >>= 1) s += __shfl_xor_sync(0xffffffffu, s, o);

    const float inv = 1.0f / s;
    const float a[3] = { e0 * inv, e1 * inv, e2 * inv };

    int* ei = g_eidx + (size_t)w * DD;
    float* av = g_aval + (size_t)w * DD;
    const unsigned lmask = (1u << lane) - 1u;
    int base = 0;
    #pragma unroll
    for (int sct = 0; sct < 3; ++sct) {
        const bool keep = a[sct] > ATHRESH;
        const unsigned mask = __ballot_sync(0xffffffffu, keep);
        if (keep) {
            const int idx = base + __popc(mask & lmask);
            ei[idx] = lane + 32*sct;
            av[idx] = a[sct];
        }
        base += __popc(mask);
    }
    if (lane == 0) g_nnz[w] = base;
}

// ===========================================================================
// Kernel C: out[b,c,p,d] = gamma * sum_{k in list(d)} a_k * V[c,e_k] + x[c,p,d]
// V = Wv X_p + bv (R3 FFMA2 math). Top-2 list entries cached in REGISTERS
// per thread (each thread owns 3 d-rows); nnz>2 tail read from global (rare).
// SMEM ~88KB -> 2 CTAs/SM.
// ===========================================================================
#define VTS 98
#define O_WV  0
#define O_X0  (O_WV + CC*CC*4)                  // 16384
#define O_V   (O_X0 + 2*CC*DD*4)                // 65536
#define O_TOTAL (O_V + CC*VTS*4)                // 90624 bytes

__global__ void __launch_bounds__(256, 2) out_k(
    const float* __restrict__ x, const float* __restrict__ Wv,
    const float* __restrict__ bv, const float* __restrict__ gamma,
    float* __restrict__ out)
{
    extern __shared__ __align__(16) unsigned char osm[];
    float* sWv  = (float*)(osm + O_WV);
    float* sXb[2] = { (float*)(osm + O_X0), (float*)(osm + O_X0) + CC*DD };
    float* sV   = (float*)(osm + O_V);          // [c][e] stride 98

    const int t  = threadIdx.x;
    const int b  = blockIdx.y;
    const int p0 = blockIdx.x * PCOUT;
    const int tx = t & 15;                      // e-group for V compute
    const int ty = t >> 4;                      // c-group for V compute
    const int exb = 6 * tx;
    const int lane = t & 31;
    const int wrp  = t >> 5;

    for (int i = t; i < CC*CC; i += 256) sWv[i] = Wv[i];

    // ---- cache top-2 attn entries per owned d-row in registers ----
    int   nL[3], e0L[3], e1L[3];
    float a0L[3], a1L[3];
    #pragma unroll
    for (int dd = 0; dd < 3; ++dd) {
        const int d = lane + 32*dd;
        const int w = b*DD + d;
        const int n = g_nnz[w];
        nL[dd]  = n;
        e0L[dd] = g_eidx[(size_t)w*DD];
        a0L[dd] = g_aval[(size_t)w*DD];
        e1L[dd] = (n > 1) ? g_eidx[(size_t)w*DD + 1] : 0;
        a1L[dd] = (n > 1) ? g_aval[(size_t)w*DD + 1] : 0.f;
    }

    const float g = gamma[0];
    float bvv[4];
    #pragma unroll
    for (int k = 0; k < 4; ++k) bvv[k] = bv[4*ty + k];

    const float* xb = x   + (size_t)b * CPD;
    float*       ob = out + (size_t)b * CPD;

    float2 r[12];
    #define LDG_SLAB(P)  {                                                      \
        const float* xp = xb + (size_t)(P) * DD;                                \
        _Pragma("unroll")                                                       \
        for (int rr = 0; rr < 12; ++rr) {                                       \
            int i2 = t + rr*256;                                                \
            int c = i2 / 48, dp = i2 % 48;                                      \
            r[rr] = *reinterpret_cast<const float2*>(xp + (size_t)c * PDSTRIDE + 2*dp); } }
    #define STS_SLAB(BUF) {                                                     \
        _Pragma("unroll")                                                       \
        for (int rr = 0; rr < 12; ++rr) {                                       \
            int i2 = t + rr*256;                                                \
            int c = i2 / 48, dp = i2 % 48;                                      \
            *reinterpret_cast<float2*>(&(BUF)[c*DD + 2*dp]) = r[rr]; } }

    LDG_SLAB(p0);
    STS_SLAB(sXb[0]);
    __syncthreads();                            // Wv + X0 visible

    for (int pp = 0; pp < PCOUT; ++pp) {
        const int p = p0 + pp;
        const float* sX = sXb[pp & 1];

        if (pp + 1 < PCOUT) LDG_SLAB(p0 + pp + 1);

        // ---- V = Wv X + bv  (4 c x 3 e-pairs per thread), R3 math ----
        {
            u64 vv[4][3];
            #pragma unroll
            for (int k = 0; k < 4; ++k)
                #pragma unroll
                for (int j = 0; j < 3; ++j) vv[k][j] = bc2(bvv[k]);

            #pragma unroll 2
            for (int c2 = 0; c2 < CC; c2 += 2) {
                u64 x0[3], x1[3];
                #pragma unroll
                for (int j = 0; j < 3; ++j) {
                    x0[j] = *reinterpret_cast<const u64*>(&sX[c2*DD + exb + 2*j]);
                    x1[j] = *reinterpret_cast<const u64*>(&sX[(c2+1)*DD + exb + 2*j]);
                }
                #pragma unroll
                for (int k = 0; k < 4; ++k) {
                    const u64 w2 = *reinterpret_cast<const u64*>(&sWv[(4*ty + k)*CC + c2]);
                    float wlo, whi; up2(wlo, whi, w2);
                    const u64 wb0 = bc2(wlo), wb1 = bc2(whi);
                    #pragma unroll
                    for (int j = 0; j < 3; ++j) {
                        vv[k][j] = ffma2(wb0, x0[j], vv[k][j]);
                        vv[k][j] = ffma2(wb1, x1[j], vv[k][j]);
                    }
                }
            }
            #pragma unroll
            for (int k = 0; k < 4; ++k)
                #pragma unroll
                for (int j = 0; j < 3; ++j)
                    *reinterpret_cast<u64*>(&sV[(4*ty + k)*VTS + exb + 2*j]) = vv[k][j];
        }
        __syncthreads();                        // V ready

        // ---- gather from registers: lanes over d (coalesced STG), warps over c ----
        #pragma unroll
        for (int ci = 0; ci < 8; ++ci) {
            const int c = wrp + 8*ci;
            const float* vrow = &sV[c*VTS];
            const float* xrow = &sX[c*DD];
            float* orow = ob + (size_t)c * PDSTRIDE + (size_t)p * DD;
            #pragma unroll
            for (int dd = 0; dd < 3; ++dd) {
                const int d = lane + 32*dd;
                float acc = a0L[dd] * vrow[e0L[dd]];
                if (nL[dd] > 1) acc = fmaf(a1L[dd], vrow[e1L[dd]], acc);
                if (nL[dd] > 2) {               // rare exact tail from global
                    const size_t w = (size_t)(b*DD + d) * DD;
                    for (int k = 2; k < nL[dd]; ++k)
                        acc = fmaf(g_aval[w + k], vrow[g_eidx[w + k]], acc);
                }
                orow[d] = fmaf(g, acc, xrow[d]);
            }
        }

        if (pp + 1 < PCOUT) STS_SLAB(sXb[(pp + 1) & 1]);
        __syncthreads();                        // gather done; next X ready
    }
    #undef LDG_SLAB
    #undef STS_SLAB
}

// ---------------------------------------------------------------------------
extern "C" void kernel_launch(void* const* d_in, const int* in_sizes, int n_in,
                              void* d_out, int out_size)
{
    const float* x  = (const float*)d_in[0];
    const float* Wq = (const float*)d_in[1];
    const float* bq = (const float*)d_in[2];
    const float* Wk = (const float*)d_in[3];
    const float* bk = (const float*)d_in[4];
    const float* Wv = (const float*)d_in[5];
    const float* bv = (const float*)d_in[6];
    const float* gm = (const float*)d_in[7];
    float* out = (float*)d_out;

    void* eptr = nullptr;
    cudaGetSymbolAddress(&eptr, g_energy);
    cudaMemsetAsync(eptr, 0, sizeof(double)*BB*DD*DD, 0);

    energy_k<<<dim3(PP/PCHUNK, BB), 256>>>(x, Wq, bq, Wk, bk);

    softmax_k<<<(BB*DD*32 + 127)/128, 128>>>();

    cudaFuncSetAttribute(out_k, cudaFuncAttributeMaxDynamicSharedMemorySize, O_TOTAL);
    out_k<<<dim3(PP/PCOUT, BB), 256, O_TOTAL>>>(x, Wv, bv, gm, out);
}